// round 9
// baseline (speedup 1.0000x reference)
#include <cuda_runtime.h>

#define TPB  128    // threads per CTA: warps 0-1 = "top", warps 2-3 = "bottom"
#define NB   64     // batches per CTA (2 threads each)
#define STR  65     // padded shared row stride
#define NN   64     // unknowns
#define NP   65
#define LAM3  1e-4f
#define RIDGE 1e-4f

// DTD band coefficients, a in [1,64]:
__host__ __device__ __forceinline__ constexpr float C0f(int a) {
    return (a == 1) ? 10.f : (a == 2) ? 19.f :
           (a <= 61) ? 20.f : (a == 62) ? 19.f : (a == 63) ? 10.f : 1.f;
}
__host__ __device__ __forceinline__ constexpr float C1f(int a) {
    return (a == 1) ? -12.f : (a <= 61) ? -15.f :
           (a == 62) ? -12.f : (a == 63) ? -3.f : 0.f;
}
__host__ __device__ __forceinline__ constexpr float C2f(int a) {
    return (a <= 61) ? 6.f : (a == 62) ? 3.f : 0.f;
}
__host__ __device__ __forceinline__ constexpr float C3f(int a) {
    return (a <= 61) ? -1.f : 0.f;
}
// diag of lhs at var p (0..63):
__host__ __device__ __forceinline__ constexpr float diagf(int p) {
    return ((p < 63) ? 2.f : 1.f) + LAM3 * C0f(p + 1) + RIDGE;
}

// Shared layout:
//  s4  : 64 rows * NB float4  (rows 0..30 top pk, rows 32..61 bottom pk)
//  sth : 65 rows * STR        theta
//  sgx : 64 rows * STR        2*dxy.x
//  sgy : 64 rows * STR        2*dxy.y
//  sou : 65 rows * STR        output staging
//  sxc : 18 * NB              central exchange (top items 0..8, bottom 9..17)
#define S4_F4    (64*NB)
#define SMEM_BYTES (S4_F4*16 + (65*STR + 2*64*STR + 65*STR + 18*NB)*4)

__global__ __launch_bounds__(TPB, 1) void AlpamayoR1_solve_kernel(
    const float* __restrict__ dxy,
    const float* __restrict__ theta,
    const float* __restrict__ v0,
    float* __restrict__ out, int B)
{
    extern __shared__ float4 smem4[];
    float4* s4  = smem4;
    float*  sth = (float*)(s4 + S4_F4);
    float*  sgx = sth + 65*STR;
    float*  sgy = sgx + 64*STR;
    float*  sou = sgy + 64*STR;
    float*  sxc = sou + 65*STR;

    const int t  = threadIdx.x;
    const int b0 = blockIdx.x * NB;
    const bool isTop = (t < 64);
    const int col = isTop ? t : (t - 64);   // local batch

    // ---- staging: coalesced float4 loads, transpose into shared ----
    {
        const float4* th4 = (const float4*)(theta + (size_t)b0 * NP);
        for (int i = t; i < (NB * NP) / 4; i += TPB) {   // 1040
            float4 v = th4[i];
            int f = 4 * i;
            int bl0 = f / NP, k0 = f - bl0 * NP;
            sth[k0 * STR + bl0] = v.x;
            int f1 = f + 1; int bl1 = f1 / NP, k1 = f1 - bl1 * NP;
            sth[k1 * STR + bl1] = v.y;
            int f2 = f + 2; int bl2 = f2 / NP, k2 = f2 - bl2 * NP;
            sth[k2 * STR + bl2] = v.z;
            int f3 = f + 3; int bl3 = f3 / NP, k3 = f3 - bl3 * NP;
            sth[k3 * STR + bl3] = v.w;
        }
        const float4* dx4 = (const float4*)(dxy + (size_t)b0 * NN * 2);
        #pragma unroll 4
        for (int i = t; i < (NB * NN) / 2; i += TPB) {   // 2048
            float4 v = dx4[i];
            int bl = i >> 5;
            int s0 = (i & 31) * 2;
            sgx[s0 * STR + bl]       = 2.f * v.x;
            sgy[s0 * STR + bl]       = 2.f * v.y;
            sgx[(s0 + 1) * STR + bl] = 2.f * v.z;
            sgy[(s0 + 1) * STR + bl] = 2.f * v.w;
        }
    }
    float v0v = 0.f;
    if (isTop) v0v = v0[b0 + col];
    __syncthreads();

    float x31, x32, x33;   // central unknowns (vars 31,32,33)

    if (isTop) {
        // ======== TOP HALF: vars 0..30, central assembly ========
        float e[34], rh[34];            // e[0..33], rh[0..33]
        {
            float thp = sth[col];
            float sp, cp; __sincosf(thp, &sp, &cp);
            float gxp = sgx[col], gyp = sgy[col];
            #pragma unroll
            for (int k = 1; k <= 34; ++k) {
                float th = sth[k * STR + col];
                float s, c; __sincosf(th, &s, &c);
                float gx = sgx[k * STR + col];
                float gy = sgy[k * STR + col];
                e [k - 1] = cp * c + sp * s;
                rh[k - 1] = c * (gxp + gx) + s * (gyp + gy);
                cp = c; sp = s; gxp = gx; gyp = gy;
            }
            rh[0] -= (e[0] - 3.f * LAM3) * v0v;
            rh[1] -= 3.f * LAM3 * v0v;
            rh[2] += LAM3 * v0v;
        }

        float L1p = 0.f, L2p1 = 0.f, L2p2 = 0.f;
        float L3p1 = 0.f, L3p2 = 0.f, L3p3 = 0.f;
        float zp1 = 0.f, zp2 = 0.f, zp3 = 0.f;
        #pragma unroll
        for (int j = 0; j <= 30; ++j) {
            float a0  = diagf(j);
            float d   = a0 - L1p * L1p - L2p2 * L2p2 - L3p3 * L3p3;
            float inv = rsqrtf(d);
            float s1v = e[j + 1] + LAM3 * C1f(j + 1) - L2p1 * L1p - L3p2 * L2p2;
            float s2v = LAM3 * C2f(j + 1) - L3p1 * L1p;
            float s3v = LAM3 * C3f(j + 1);
            float L1 = s1v * inv, L2 = s2v * inv, L3 = s3v * inv;
            float z  = (rh[j] - L1p * zp1 - L2p2 * zp2 - L3p3 * zp3) * inv;
            float4 pk; pk.x = L1 * inv; pk.y = L2 * inv; pk.z = L3 * inv; pk.w = z * inv;
            s4[j * NB + col] = pk;
            L3p3 = L3p2; L3p2 = L3p1; L3p1 = L3;
            L2p2 = L2p1; L2p1 = L2; L1p = L1;
            zp3 = zp2; zp2 = zp1; zp1 = z;
        }
        // central assembly (A_c minus top contributions)
        sxc[0 * NB + col] = diagf(31) - (L1p*L1p + L2p2*L2p2 + L3p3*L3p3);          // S11t
        sxc[1 * NB + col] = e[32] + LAM3 * C1f(32) - (L2p1*L1p + L3p2*L2p2);        // S12t
        sxc[2 * NB + col] = LAM3 * C2f(32) - (L3p1*L1p);                            // S13t
        sxc[3 * NB + col] = diagf(32) - (L2p1*L2p1 + L3p2*L3p2);                    // S22t
        sxc[4 * NB + col] = e[33] + LAM3 * C1f(33) - (L3p1*L2p1);                   // S23t
        sxc[5 * NB + col] = diagf(33) - (L3p1*L3p1);                                // S33t
        sxc[6 * NB + col] = rh[31] - (L1p*zp1 + L2p2*zp2 + L3p3*zp3);               // r1t
        sxc[7 * NB + col] = rh[32] - (L2p1*zp1 + L3p2*zp2);                         // r2t
        sxc[8 * NB + col] = rh[33] - (L3p1*zp1);                                    // r3t
        __syncthreads();

        // central 3x3 solve
        float S11 = sxc[0*NB+col] - sxc[ 9*NB+col];
        float S12 = sxc[1*NB+col] - sxc[10*NB+col];
        float S13 = sxc[2*NB+col] - sxc[11*NB+col];
        float S22 = sxc[3*NB+col] - sxc[12*NB+col];
        float S23 = sxc[4*NB+col] - sxc[13*NB+col];
        float S33 = sxc[5*NB+col] - sxc[14*NB+col];
        float r1  = sxc[6*NB+col] - sxc[15*NB+col];
        float r2  = sxc[7*NB+col] - sxc[16*NB+col];
        float r3  = sxc[8*NB+col] - sxc[17*NB+col];
        float i1 = rsqrtf(S11);
        float l21 = S12 * i1, l31 = S13 * i1;
        float i2 = rsqrtf(S22 - l21 * l21);
        float l32 = (S23 - l31 * l21) * i2;
        float i3 = rsqrtf(S33 - l31 * l31 - l32 * l32);
        float u1 = r1 * i1;
        float u2 = (r2 - l21 * u1) * i2;
        float u3 = (r3 - l31 * u1 - l32 * u2) * i3;
        x33 = u3 * i3;
        x32 = (u2 - l32 * x33) * i2;
        x31 = (u1 - l21 * x32 - l31 * x33) * i1;

        // back substitution for vars 30..0
        float y1 = x31, y2 = x32, y3 = x33;
        #pragma unroll
        for (int j = 30; j >= 0; --j) {
            float4 pk = s4[j * NB + col];
            float tmp = pk.w - pk.y * y2 - pk.z * y3;
            float y   = tmp - pk.x * y1;
            sou[(j + 1) * STR + col] = y;
            y3 = y2; y2 = y1; y1 = y;
        }
        sou[col] = v0v;
        sou[32 * STR + col] = x31;
        sou[33 * STR + col] = x32;
        sou[34 * STR + col] = x33;
    } else {
        // ======== BOTTOM HALF: vars 63..34 (reversed matrix) ========
        float ebt[30], rhb[30];   // ebt[i]=e[63-i], rhb[i]=rh[63-i], i=0..29
        {
            float thp = sth[64 * STR + col];     // theta_64
            float sp, cp; __sincosf(thp, &sp, &cp);
            float gxp = 0.f, gyp = 0.f;          // g_64 doesn't exist
            #pragma unroll
            for (int i = 0; i < 30; ++i) {
                int k = 64 - i;                  // pair (th_{k-1}, th_k)
                float th = sth[(k - 1) * STR + col];
                float s, c; __sincosf(th, &s, &c);
                float gx = sgx[(k - 1) * STR + col];
                float gy = sgy[(k - 1) * STR + col];
                ebt[i] = c * cp + s * sp;                    // e[k-1] = e[63-i]
                rhb[i] = cp * (gx + gxp) + sp * (gy + gyp);  // rh[k-1]
                cp = c; sp = s; gxp = gx; gyp = gy;
            }
        }

        float L1p = 0.f, L2p1 = 0.f, L2p2 = 0.f;
        float L3p1 = 0.f, L3p2 = 0.f, L3p3 = 0.f;
        float zp1 = 0.f, zp2 = 0.f, zp3 = 0.f;
        #pragma unroll
        for (int j = 0; j <= 29; ++j) {          // eliminates var 63-j
            float a0  = ((j == 0) ? 1.f : 2.f) + LAM3 * C0f(64 - j) + RIDGE;
            float d   = a0 - L1p * L1p - L2p2 * L2p2 - L3p3 * L3p3;
            float inv = rsqrtf(d);
            float s1v = ebt[j] + LAM3 * C1f(63 - j) - L2p1 * L1p - L3p2 * L2p2;
            float s2v = LAM3 * C2f(62 - j) - L3p1 * L1p;
            float s3v = LAM3 * C3f(61 - j);
            float L1 = s1v * inv, L2 = s2v * inv, L3 = s3v * inv;
            float z  = (rhb[j] - L1p * zp1 - L2p2 * zp2 - L3p3 * zp3) * inv;
            float4 pk; pk.x = L1 * inv; pk.y = L2 * inv; pk.z = L3 * inv; pk.w = z * inv;
            s4[(32 + j) * NB + col] = pk;
            L3p3 = L3p2; L3p2 = L3p1; L3p1 = L3;
            L2p2 = L2p1; L2p1 = L2; L1p = L1;
            zp3 = zp2; zp2 = zp1; zp1 = z;
        }
        // bottom contributions (reversed: rev rows 30,31,32 = orig 33,32,31)
        sxc[14 * NB + col] = L1p*L1p + L2p2*L2p2 + L3p3*L3p3;     // to S33
        sxc[13 * NB + col] = L2p1*L1p + L3p2*L2p2;                // to S23
        sxc[11 * NB + col] = L3p1*L1p;                            // to S13
        sxc[12 * NB + col] = L2p1*L2p1 + L3p2*L3p2;               // to S22
        sxc[10 * NB + col] = L3p1*L2p1;                           // to S12
        sxc[ 9 * NB + col] = L3p1*L3p1;                           // to S11
        sxc[17 * NB + col] = L1p*zp1 + L2p2*zp2 + L3p3*zp3;       // to r3
        sxc[16 * NB + col] = L2p1*zp1 + L3p2*zp2;                 // to r2
        sxc[15 * NB + col] = L3p1*zp1;                            // to r1
        __syncthreads();

        // central 3x3 solve (redundant with top)
        float S11 = sxc[0*NB+col] - sxc[ 9*NB+col];
        float S12 = sxc[1*NB+col] - sxc[10*NB+col];
        float S13 = sxc[2*NB+col] - sxc[11*NB+col];
        float S22 = sxc[3*NB+col] - sxc[12*NB+col];
        float S23 = sxc[4*NB+col] - sxc[13*NB+col];
        float S33 = sxc[5*NB+col] - sxc[14*NB+col];
        float r1  = sxc[6*NB+col] - sxc[15*NB+col];
        float r2  = sxc[7*NB+col] - sxc[16*NB+col];
        float r3  = sxc[8*NB+col] - sxc[17*NB+col];
        float i1 = rsqrtf(S11);
        float l21 = S12 * i1, l31 = S13 * i1;
        float i2 = rsqrtf(S22 - l21 * l21);
        float l32 = (S23 - l31 * l21) * i2;
        float i3 = rsqrtf(S33 - l31 * l31 - l32 * l32);
        float u1 = r1 * i1;
        float u2 = (r2 - l21 * u1) * i2;
        float u3 = (r3 - l31 * u1 - l32 * u2) * i3;
        x33 = u3 * i3;
        x32 = (u2 - l32 * x33) * i2;
        x31 = (u1 - l21 * x32 - l31 * x33) * i1;

        // back substitution for vars 34..63 (rev coords)
        float y1 = x33, y2 = x32, y3 = x31;   // x'_{30},x'_{31},x'_{32}
        #pragma unroll
        for (int j = 29; j >= 0; --j) {
            float4 pk = s4[(32 + j) * NB + col];
            float tmp = pk.w - pk.y * y2 - pk.z * y3;
            float y   = tmp - pk.x * y1;      // x'_j = x_{63-j}
            sou[(64 - j) * STR + col] = y;    // out index (63-j)+1
            y3 = y2; y2 = y1; y1 = y;
        }
    }
    __syncthreads();

    // ---- coalesced float4 store ----
    {
        float4* out4 = (float4*)(out + (size_t)b0 * NP);
        for (int i = t; i < (NB * NP) / 4; i += TPB) {
            int f = 4 * i;
            int bl0 = f / NP, k0 = f - bl0 * NP;
            int f1 = f + 1; int bl1 = f1 / NP, k1 = f1 - bl1 * NP;
            int f2 = f + 2; int bl2 = f2 / NP, k2 = f2 - bl2 * NP;
            int f3 = f + 3; int bl3 = f3 / NP, k3 = f3 - bl3 * NP;
            float4 v;
            v.x = sou[k0 * STR + bl0];
            v.y = sou[k1 * STR + bl1];
            v.z = sou[k2 * STR + bl2];
            v.w = sou[k3 * STR + bl3];
            out4[i] = v;
        }
    }
}

extern "C" void kernel_launch(void* const* d_in, const int* in_sizes, int n_in,
                              void* d_out, int out_size) {
    const float* dxy   = (const float*)d_in[0];
    const float* theta = (const float*)d_in[1];
    const float* v0    = (const float*)d_in[2];
    float* out = (float*)d_out;
    int B = in_sizes[2];

    cudaFuncSetAttribute(AlpamayoR1_solve_kernel,
                         cudaFuncAttributeMaxDynamicSharedMemorySize, SMEM_BYTES);
    int grid = (B + NB - 1) / NB;
    AlpamayoR1_solve_kernel<<<grid, TPB, SMEM_BYTES>>>(dxy, theta, v0, out, B);
}

// round 10
// speedup vs baseline: 1.0586x; 1.0586x over previous
#include <cuda_runtime.h>

#define TPB  256
#define NBT  64
#define STR  65
#define NN   64
#define NP   65
#define LAM3  1e-4f
#define RIDGE 1e-4f

__host__ __device__ __forceinline__ float C0f(int a) {
    return (a == 1) ? 10.f : (a == 2) ? 19.f :
           (a <= 61) ? 20.f : (a == 62) ? 19.f : (a == 63) ? 10.f : 1.f;
}
__host__ __device__ __forceinline__ float C1f(int a) {
    return (a == 1) ? -12.f : (a <= 61) ? -15.f :
           (a == 62) ? -12.f : (a == 63) ? -3.f : 0.f;
}
__host__ __device__ __forceinline__ float C2f(int a) {
    return (a <= 61) ? 6.f : (a == 62) ? 3.f : 0.f;
}
__host__ __device__ __forceinline__ float C3f(int a) {
    return (a <= 61) ? -1.f : 0.f;
}
__host__ __device__ __forceinline__ float diagf(int p) {
    return ((p < 63) ? 2.f : 1.f) + LAM3 * C0f(p + 1) + RIDGE;
}

#define S4ROWS   56
#define STH_F    (NP*STR)
#define SG_F     (NN*STR)
#define SOU_F    (NP*STR)
#define SGR_F    (3*3*3*64)
#define SGL_F    (3*14*3*64)
#define SXC_F    (99*64)
#define SMEM_BYTES (S4ROWS*64*16 + (STH_F + 2*SG_F + SOU_F + SGR_F + SGL_F + SXC_F)*4)
#define IX(i,j) ((i)*((i)+1)/2 + (j))

__global__ __launch_bounds__(TPB, 1) void AlpamayoR1_solve_kernel(
    const float* __restrict__ dxy,
    const float* __restrict__ theta,
    const float* __restrict__ v0,
    float* __restrict__ out, int B)
{
    extern __shared__ float4 smem4[];
    float4* s4  = smem4;
    float*  sth = (float*)(s4 + S4ROWS*64);
    float*  sgx = sth + STH_F;
    float*  sgy = sgx + SG_F;
    float*  sou = sgy + SG_F;
    float*  sgr = sou + SOU_F;
    float*  sgl = sgr + SGR_F;
    float*  sxc = sgl + SGL_F;

    const int t    = threadIdx.x;
    const int role = t >> 6;
    const int col  = t & 63;
    const int b0   = blockIdx.x * NBT;

    // ---- staging ----
    {
        const float4* th4 = (const float4*)(theta + (size_t)b0 * NP);
        for (int i = t; i < (NBT * NP) / 4; i += TPB) {
            float4 v = th4[i];
            int f = 4 * i;
            int bl0 = f / NP, k0 = f - bl0 * NP;       sth[k0 * STR + bl0] = v.x;
            int f1 = f + 1, bl1 = f1 / NP, k1 = f1 - bl1 * NP; sth[k1 * STR + bl1] = v.y;
            int f2 = f + 2, bl2 = f2 / NP, k2 = f2 - bl2 * NP; sth[k2 * STR + bl2] = v.z;
            int f3 = f + 3, bl3 = f3 / NP, k3 = f3 - bl3 * NP; sth[k3 * STR + bl3] = v.w;
        }
        const float4* dx4 = (const float4*)(dxy + (size_t)b0 * NN * 2);
        #pragma unroll 4
        for (int i = t; i < (NBT * NN) / 2; i += TPB) {
            float4 v = dx4[i];
            int bl = i >> 5, s0 = (i & 31) * 2;
            sgx[s0 * STR + bl]       = 2.f * v.x;
            sgy[s0 * STR + bl]       = 2.f * v.y;
            sgx[(s0 + 1) * STR + bl] = 2.f * v.z;
            sgy[(s0 + 1) * STR + bl] = 2.f * v.w;
        }
    }
    float v0v = (role == 0) ? v0[b0 + col] : 0.f;
    __syncthreads();

    const int J0 = role * 17;
    const int partlen = (role == 3) ? 13 : 14;
    const bool hasL = (role > 0), hasR = (role < 3);

    // ---- Phase 1: sincos -> e, rhs in registers ----
    float earr[17], rarr[17];
    float e49 = 0.f, e50 = 0.f, rh48 = 0.f, rh49 = 0.f, rh50 = 0.f;
    if (role < 3) {
        float thp = sth[J0 * STR + col];
        float sp, cp; __sincosf(thp, &sp, &cp);
        float gxp = sgx[J0 * STR + col], gyp = sgy[J0 * STR + col];
        #pragma unroll
        for (int i = 1; i <= 17; ++i) {
            int k = J0 + i;
            float th = sth[k * STR + col];
            float s, c; __sincosf(th, &s, &c);
            float gx = sgx[k * STR + col], gy = sgy[k * STR + col];
            earr[i - 1] = cp * c + sp * s;
            rarr[i - 1] = c * (gxp + gx) + s * (gyp + gy);
            cp = c; sp = s; gxp = gx; gyp = gy;
        }
        if (role == 0) {
            rarr[0] -= (earr[0] - 3.f * LAM3) * v0v;
            rarr[1] -= 3.f * LAM3 * v0v;
            rarr[2] += LAM3 * v0v;
        }
    } else {
        float thp = sth[48 * STR + col];
        float sp, cp; __sincosf(thp, &sp, &cp);
        float gxp = sgx[48 * STR + col], gyp = sgy[48 * STR + col];
        #pragma unroll
        for (int i = 1; i <= 16; ++i) {
            int k = 48 + i;
            float th = sth[k * STR + col];
            float s, c; __sincosf(th, &s, &c);
            float gx = 0.f, gy = 0.f;
            if (k <= 63) { gx = sgx[k * STR + col]; gy = sgy[k * STR + col]; }
            float ee = cp * c + sp * s;                 // e[47+i]
            float rr = c * (gxp + gx) + s * (gyp + gy); // rh[47+i]
            if (i == 2) e49 = ee; else if (i == 3) e50 = ee;
            else if (i >= 4) earr[i - 4] = ee;
            if (i == 1) rh48 = rr; else if (i == 2) rh49 = rr;
            else if (i == 3) rh50 = rr; else if (i >= 4) rarr[i - 4] = rr;
            cp = c; sp = s; gxp = gx; gyp = gy;
        }
        #pragma unroll
        for (int i = 13; i < 17; ++i) { earr[i] = 0.f; rarr[i] = 0.f; }
    }

    // ---- border coupling constants ----
    float aL0x=0,aL0y=0,aL0z=0, aL1y=0,aL1z=0, aL2z=0;
    if (hasL) {
        aL0x = LAM3 * C3f(J0 - 2);
        aL0y = LAM3 * C2f(J0 - 1);
        aL0z = earr[0] + LAM3 * C1f(J0);
        aL1y = LAM3 * C3f(J0 - 1);
        aL1z = LAM3 * C2f(J0);
        aL2z = LAM3 * C3f(J0);
    }
    float aR0x=0, aR1x=0,aR1y=0, aR2x=0,aR2y=0,aR2z=0;
    if (hasR) {
        int Je = J0 + 13;
        aR0x = LAM3 * C3f(Je - 1);
        aR1x = LAM3 * C2f(Je);
        aR1y = LAM3 * C3f(Je);
        aR2x = earr[14] + LAM3 * C1f(Je + 1);
        aR2y = LAM3 * C2f(Je + 1);
        aR2z = LAM3 * C3f(Je + 1);
    }

    // ---- Phase 2: bordered band Cholesky ----
    float L1p=0.f, L2p1=0.f, L2p2=0.f, L3p1=0.f, L3p2=0.f, L3p3=0.f;
    float zp1=0.f, zp2=0.f, zp3=0.f;
    float gl1x=0,gl1y=0,gl1z=0, gl2x=0,gl2y=0,gl2z=0, gl3x=0,gl3y=0,gl3z=0;
    float gr1x=0,gr1y=0,gr1z=0, gr2x=0,gr2y=0,gr2z=0, gr3x=0,gr3y=0,gr3z=0;
    float sl00=0,sl01=0,sl02=0,sl11=0,sl12=0,sl22=0;
    float sr00=0,sr01=0,sr02=0,sr11=0,sr12=0,sr22=0;
    float sx00=0,sx01=0,sx02=0,sx10=0,sx11=0,sx12=0,sx20=0,sx21=0,sx22=0;
    float rl0=0,rl1=0,rl2=0, rr0=0,rr1=0,rr2=0;

    #pragma unroll
    for (int jj = 0; jj < 14; ++jj) {
        if (jj < partlen) {
            int j = J0 + jj;
            float d   = diagf(j) - L1p*L1p - L2p2*L2p2 - L3p3*L3p3;
            float inv = rsqrtf(d);
            float s1v = (jj < partlen - 1)
                      ? (earr[jj + 1] + LAM3 * C1f(j + 1) - L2p1*L1p - L3p2*L2p2) : 0.f;
            float s2v = (jj < partlen - 2) ? (LAM3 * C2f(j + 1) - L3p1*L1p) : 0.f;
            float s3v = (jj < partlen - 3) ? (LAM3 * C3f(j + 1)) : 0.f;
            float L1 = s1v * inv, L2 = s2v * inv, L3 = s3v * inv;
            float z  = (rarr[jj] - L1p*zp1 - L2p2*zp2 - L3p3*zp3) * inv;

            float4 pk;
            pk.x = L1 * inv; pk.y = L2 * inv; pk.z = L3 * inv; pk.w = z * inv;
            s4[(role * 14 + jj) * 64 + col] = pk;

            float glx=0, gly=0, glz=0;
            if (hasL) {
                float ax = (jj == 0) ? aL0x : 0.f;
                float ay = (jj == 0) ? aL0y : (jj == 1) ? aL1y : 0.f;
                float az = (jj == 0) ? aL0z : (jj == 1) ? aL1z : (jj == 2) ? aL2z : 0.f;
                glx = (ax - L1p*gl1x - L2p2*gl2x - L3p3*gl3x) * inv;
                gly = (ay - L1p*gl1y - L2p2*gl2y - L3p3*gl3y) * inv;
                glz = (az - L1p*gl1z - L2p2*gl2z - L3p3*gl3z) * inv;
                sl00 += glx*glx; sl01 += glx*gly; sl02 += glx*glz;
                sl11 += gly*gly; sl12 += gly*glz; sl22 += glz*glz;
                rl0 += glx*z; rl1 += gly*z; rl2 += glz*z;
                int gb = (((role - 1) * 14 + jj) * 3) * 64 + col;
                sgl[gb]       = glx * inv;
                sgl[gb + 64]  = gly * inv;
                sgl[gb + 128] = glz * inv;
            }
            if (hasR && jj >= 11) {
                float ax = (jj == 11) ? aR0x : (jj == 12) ? aR1x : aR2x;
                float ay = (jj == 12) ? aR1y : (jj == 13) ? aR2y : 0.f;
                float az = (jj == 13) ? aR2z : 0.f;
                float grx = (ax - L1p*gr1x - L2p2*gr2x - L3p3*gr3x) * inv;
                float gry = (ay - L1p*gr1y - L2p2*gr2y - L3p3*gr3y) * inv;
                float grz = (az - L1p*gr1z - L2p2*gr2z - L3p3*gr3z) * inv;
                sr00 += grx*grx; sr01 += grx*gry; sr02 += grx*grz;
                sr11 += gry*gry; sr12 += gry*grz; sr22 += grz*grz;
                rr0 += grx*z; rr1 += gry*z; rr2 += grz*z;
                if (hasL) {
                    sx00 += glx*grx; sx01 += glx*gry; sx02 += glx*grz;
                    sx10 += gly*grx; sx11 += gly*gry; sx12 += gly*grz;
                    sx20 += glz*grx; sx21 += glz*gry; sx22 += glz*grz;
                }
                int gb = ((role * 3 + (jj - 11)) * 3) * 64 + col;
                sgr[gb]       = grx * inv;
                sgr[gb + 64]  = gry * inv;
                sgr[gb + 128] = grz * inv;
                gr3x=gr2x; gr3y=gr2y; gr3z=gr2z;
                gr2x=gr1x; gr2y=gr1y; gr2z=gr1z;
                gr1x=grx;  gr1y=gry;  gr1z=grz;
            }
            if (hasL) {
                gl3x=gl2x; gl3y=gl2y; gl3z=gl2z;
                gl2x=gl1x; gl2y=gl1y; gl2z=gl1z;
                gl1x=glx;  gl1y=gly;  gl1z=glz;
            }
            L3p3=L3p2; L3p2=L3p1; L3p1=L3;
            L2p2=L2p1; L2p1=L2; L1p=L1;
            zp3=zp2; zp2=zp1; zp1=z;
        }
    }

    // ---- write Schur pieces + interface originals ----
    #define SX(i) sxc[(i)*64 + col]
    if (role == 0) {
        SX(0)=sr00; SX(1)=sr01; SX(2)=sr02; SX(3)=sr11; SX(4)=sr12; SX(5)=sr22;
        SX(6)=rr0; SX(7)=rr1; SX(8)=rr2;
        SX(72)=diagf(14); SX(73)=earr[15]+LAM3*C1f(15); SX(74)=LAM3*C2f(15);
        SX(75)=diagf(15); SX(76)=earr[16]+LAM3*C1f(16); SX(77)=diagf(16);
        SX(78)=rarr[14]; SX(79)=rarr[15]; SX(80)=rarr[16];
    } else if (role == 1) {
        SX(9)=sl00; SX(10)=sl01; SX(11)=sl02; SX(12)=sl11; SX(13)=sl12; SX(14)=sl22;
        SX(15)=sx00; SX(16)=sx01; SX(17)=sx02; SX(18)=sx10; SX(19)=sx11; SX(20)=sx12;
        SX(21)=sx20; SX(22)=sx21; SX(23)=sx22;
        SX(24)=sr00; SX(25)=sr01; SX(26)=sr02; SX(27)=sr11; SX(28)=sr12; SX(29)=sr22;
        SX(30)=rl0; SX(31)=rl1; SX(32)=rl2;
        SX(33)=rr0; SX(34)=rr1; SX(35)=rr2;
        SX(81)=diagf(31); SX(82)=earr[15]+LAM3*C1f(32); SX(83)=LAM3*C2f(32);
        SX(84)=diagf(32); SX(85)=earr[16]+LAM3*C1f(33); SX(86)=diagf(33);
        SX(87)=rarr[14]; SX(88)=rarr[15]; SX(89)=rarr[16];
    } else if (role == 2) {
        SX(36)=sl00; SX(37)=sl01; SX(38)=sl02; SX(39)=sl11; SX(40)=sl12; SX(41)=sl22;
        SX(42)=sx00; SX(43)=sx01; SX(44)=sx02; SX(45)=sx10; SX(46)=sx11; SX(47)=sx12;
        SX(48)=sx20; SX(49)=sx21; SX(50)=sx22;
        SX(51)=sr00; SX(52)=sr01; SX(53)=sr02; SX(54)=sr11; SX(55)=sr12; SX(56)=sr22;
        SX(57)=rl0; SX(58)=rl1; SX(59)=rl2;
        SX(60)=rr0; SX(61)=rr1; SX(62)=rr2;
    } else {
        SX(63)=sl00; SX(64)=sl01; SX(65)=sl02; SX(66)=sl11; SX(67)=sl12; SX(68)=sl22;
        SX(69)=rl0; SX(70)=rl1; SX(71)=rl2;
        SX(90)=diagf(48); SX(91)=e49+LAM3*C1f(49); SX(92)=LAM3*C2f(49);
        SX(93)=diagf(49); SX(94)=e50+LAM3*C1f(50); SX(95)=diagf(50);
        SX(96)=rh48; SX(97)=rh49; SX(98)=rh50;
    }
    __syncthreads();

    // ---- 9x9 interface solve (redundant per thread) ----
    float Mm[45], rr9[9], iv9[9], z9[9], x9[9];
    Mm[IX(0,0)] = SX(72) - SX(0) - SX( 9);
    Mm[IX(1,0)] = SX(73) - SX(1) - SX(10);
    Mm[IX(2,0)] = SX(74) - SX(2) - SX(11);
    Mm[IX(1,1)] = SX(75) - SX(3) - SX(12);
    Mm[IX(2,1)] = SX(76) - SX(4) - SX(13);
    Mm[IX(2,2)] = SX(77) - SX(5) - SX(14);
    #pragma unroll
    for (int i = 0; i < 3; ++i)
        #pragma unroll
        for (int k = 0; k < 3; ++k)
            Mm[IX(3 + k, i)] = -SX(15 + i * 3 + k);
    Mm[IX(3,3)] = SX(81) - SX(24) - SX(36);
    Mm[IX(4,3)] = SX(82) - SX(25) - SX(37);
    Mm[IX(5,3)] = SX(83) - SX(26) - SX(38);
    Mm[IX(4,4)] = SX(84) - SX(27) - SX(39);
    Mm[IX(5,4)] = SX(85) - SX(28) - SX(40);
    Mm[IX(5,5)] = SX(86) - SX(29) - SX(41);
    #pragma unroll
    for (int i = 0; i < 3; ++i)
        #pragma unroll
        for (int k = 0; k < 3; ++k)
            Mm[IX(6 + k, 3 + i)] = -SX(42 + i * 3 + k);
    #pragma unroll
    for (int i = 6; i < 9; ++i)
        #pragma unroll
        for (int k = 0; k < 3; ++k)
            Mm[IX(i, k)] = 0.f;
    Mm[IX(6,6)] = SX(90) - SX(51) - SX(63);
    Mm[IX(7,6)] = SX(91) - SX(52) - SX(64);
    Mm[IX(8,6)] = SX(92) - SX(53) - SX(65);
    Mm[IX(7,7)] = SX(93) - SX(54) - SX(66);
    Mm[IX(8,7)] = SX(94) - SX(55) - SX(67);
    Mm[IX(8,8)] = SX(95) - SX(56) - SX(68);
    rr9[0] = SX(78) - SX(6) - SX(30);
    rr9[1] = SX(79) - SX(7) - SX(31);
    rr9[2] = SX(80) - SX(8) - SX(32);
    rr9[3] = SX(87) - SX(33) - SX(57);
    rr9[4] = SX(88) - SX(34) - SX(58);
    rr9[5] = SX(89) - SX(35) - SX(59);
    rr9[6] = SX(96) - SX(60) - SX(69);
    rr9[7] = SX(97) - SX(61) - SX(70);
    rr9[8] = SX(98) - SX(62) - SX(71);

    #pragma unroll
    for (int k = 0; k < 9; ++k) {
        float dk = Mm[IX(k,k)];
        #pragma unroll
        for (int w = 0; w < 9; ++w) if (w < k) dk -= Mm[IX(k,w)] * Mm[IX(k,w)];
        float ivk = rsqrtf(dk);
        iv9[k] = ivk;
        float zk = rr9[k];
        #pragma unroll
        for (int w = 0; w < 9; ++w) if (w < k) zk -= Mm[IX(k,w)] * z9[w];
        z9[k] = zk * ivk;
        #pragma unroll
        for (int i2 = k + 1; i2 < 9; ++i2) {
            float s = Mm[IX(i2,k)];
            #pragma unroll
            for (int w = 0; w < 9; ++w) if (w < k) s -= Mm[IX(i2,w)] * Mm[IX(k,w)];
            Mm[IX(i2,k)] = s * ivk;
        }
    }
    #pragma unroll
    for (int k = 8; k >= 0; --k) {
        float s = z9[k];
        #pragma unroll
        for (int i2 = 8; i2 > 0; --i2) if (i2 > k) s -= Mm[IX(i2,k)] * x9[i2];
        x9[k] = s * iv9[k];
    }

    // ---- back substitution ----
    float xL0=0,xL1=0,xL2=0, xR0=0,xR1=0,xR2=0;
    if (role == 0)      { xR0=x9[0]; xR1=x9[1]; xR2=x9[2]; }
    else if (role == 1) { xL0=x9[0]; xL1=x9[1]; xL2=x9[2]; xR0=x9[3]; xR1=x9[4]; xR2=x9[5]; }
    else if (role == 2) { xL0=x9[3]; xL1=x9[4]; xL2=x9[5]; xR0=x9[6]; xR1=x9[7]; xR2=x9[8]; }
    else                { xL0=x9[6]; xL1=x9[7]; xL2=x9[8]; }

    {
        float y1, y2, y3;
        if (hasR) { y1 = xR0; y2 = xR1; y3 = xR2; }
        else      { y1 = 0.f; y2 = 0.f; y3 = 0.f; }
        #pragma unroll
        for (int jj = 13; jj >= 0; --jj) {
            if (jj < partlen) {
                float4 pk = s4[(role * 14 + jj) * 64 + col];
                float w = pk.w;
                if (hasL) {
                    int gb = (((role - 1) * 14 + jj) * 3) * 64 + col;
                    w -= sgl[gb] * xL0 + sgl[gb + 64] * xL1 + sgl[gb + 128] * xL2;
                }
                if (hasR && jj >= 11) {
                    int gb = ((role * 3 + (jj - 11)) * 3) * 64 + col;
                    w -= sgr[gb] * xR0 + sgr[gb + 64] * xR1 + sgr[gb + 128] * xR2;
                }
                float x = w - pk.x * y1 - pk.y * y2 - pk.z * y3;
                sou[(J0 + jj + 1) * STR + col] = x;
                y3 = y2; y2 = y1; y1 = x;
            }
        }
        if (role == 0) {
            sou[col] = v0v;
            sou[15 * STR + col] = x9[0];
            sou[16 * STR + col] = x9[1];
            sou[17 * STR + col] = x9[2];
        } else if (role == 1) {
            sou[32 * STR + col] = x9[3];
            sou[33 * STR + col] = x9[4];
            sou[34 * STR + col] = x9[5];
        } else if (role == 2) {
            sou[49 * STR + col] = x9[6];
            sou[50 * STR + col] = x9[7];
            sou[51 * STR + col] = x9[8];
        }
    }
    __syncthreads();

    // ---- coalesced float4 store ----
    {
        float4* out4 = (float4*)(out + (size_t)b0 * NP);
        for (int i = t; i < (NBT * NP) / 4; i += TPB) {
            int f = 4 * i;
            int bl0 = f / NP, k0 = f - bl0 * NP;
            int f1 = f + 1, bl1 = f1 / NP, k1 = f1 - bl1 * NP;
            int f2 = f + 2, bl2 = f2 / NP, k2 = f2 - bl2 * NP;
            int f3 = f + 3, bl3 = f3 / NP, k3 = f3 - bl3 * NP;
            float4 v;
            v.x = sou[k0 * STR + bl0];
            v.y = sou[k1 * STR + bl1];
            v.z = sou[k2 * STR + bl2];
            v.w = sou[k3 * STR + bl3];
            out4[i] = v;
        }
    }
}

extern "C" void kernel_launch(void* const* d_in, const int* in_sizes, int n_in,
                              void* d_out, int out_size) {
    const float* dxy   = (const float*)d_in[0];
    const float* theta = (const float*)d_in[1];
    const float* v0    = (const float*)d_in[2];
    float* out = (float*)d_out;
    int B = in_sizes[2];

    cudaFuncSetAttribute(AlpamayoR1_solve_kernel,
                         cudaFuncAttributeMaxDynamicSharedMemorySize, SMEM_BYTES);
    int grid = (B + NBT - 1) / NBT;
    AlpamayoR1_solve_kernel<<<grid, TPB, SMEM_BYTES>>>(dxy, theta, v0, out, B);
}